// round 8
// baseline (speedup 1.0000x reference)
#include <cuda_runtime.h>
#include <cstdint>

// FPS: B=4 batches, N=8192 points, S=1024 samples.
// One persistent CTA per batch. Points + squared-distance field in registers
// (8 points/thread, packed f32x2 pairs); point table in SMEM for winner-coord
// broadcast. Exact float32 decision reproduction:
//  - running min kept in squared domain (min commutes with monotone sqrt_rn)
//  - argmax over ds = sqrt_rn(tmin), first-occurrence ties: REDUX max on sqrt
//    bits then REDUX min on qualifying index (warp stage + block stage)
//  - local tie repair: prefilter t >= rd(pred(a)^2) + exact sqrt check
//  - distance sum via packed add/mul.rn.f32x2 (bit-exact per-lane IEEE RN),
//    order (dx^2+dy^2)+dz^2, no FMA contraction
//  - local max for iteration s+1 fused into iteration s's min-update loop

#define NPTS     8192
#define NTHREADS 1024
#define SLOTS    (NPTS / NTHREADS)   // 8
#define PAIRS    (SLOTS / 2)         // 4
#define NSAMP    1024
#define NWARPS   (NTHREADS / 32)     // 32
#define FULLMASK 0xffffffffu

typedef unsigned long long u64;

__device__ __forceinline__ u64 pack2(float lo, float hi) {
    u64 r;
    asm("mov.b64 %0, {%1, %2};" : "=l"(r) : "f"(lo), "f"(hi));
    return r;
}
__device__ __forceinline__ void unpack2(u64 v, float& lo, float& hi) {
    asm("mov.b64 {%0, %1}, %2;" : "=f"(lo), "=f"(hi) : "l"(v));
}
__device__ __forceinline__ u64 add2(u64 a, u64 b) {
    u64 r;
    asm("add.rn.f32x2 %0, %1, %2;" : "=l"(r) : "l"(a), "l"(b));
    return r;
}
__device__ __forceinline__ u64 mul2(u64 a, u64 b) {
    u64 r;
    asm("mul.rn.f32x2 %0, %1, %2;" : "=l"(r) : "l"(a), "l"(b));
    return r;
}

__global__ __launch_bounds__(NTHREADS, 1)
void fps_kernel(const float* __restrict__ in, float* __restrict__ out)
{
    extern __shared__ float sm[];
    float*    px = sm;                  // [NPTS]
    float*    py = sm + NPTS;           // [NPTS]
    float*    pz = sm + 2 * NPTS;       // [NPTS]
    unsigned* wa = (unsigned*)(sm + 3 * NPTS);   // [2][NWARPS] sqrt bits
    unsigned* wi = wa + 2 * NWARPS;              // [2][NWARPS] min index

    const int tid  = threadIdx.x;
    const int lane = tid & 31;
    const int wid  = tid >> 5;

    const float* g = in + (size_t)blockIdx.x * NPTS * 3;

    // ---- load points into SMEM (one-time cost) ----
    for (int i = tid; i < NPTS; i += NTHREADS) {
        px[i] = g[3 * i + 0];
        py[i] = g[3 * i + 1];
        pz[i] = g[3 * i + 2];
    }
    __syncthreads();

    // ---- register-resident slots, packed as pairs:
    // pair j holds slots (2j, 2j+1); slot k owns index k*NTHREADS + tid ----
    u64 ppx[PAIRS], ppy[PAIRS], ppz[PAIRS];
    float tmin[SLOTS];
    #pragma unroll
    for (int j = 0; j < PAIRS; j++) {
        int i0 = (2 * j + 0) * NTHREADS + tid;
        int i1 = (2 * j + 1) * NTHREADS + tid;
        ppx[j] = pack2(px[i0], px[i1]);
        ppy[j] = pack2(py[i0], py[i1]);
        ppz[j] = pack2(pz[i0], pz[i1]);
    }

    // ---- init: squared distance to point 0; seed local max ----
    float cmax = -1.0f;
    {
        u64 nsx2 = pack2(-px[0], -px[0]);
        u64 nsy2 = pack2(-py[0], -py[0]);
        u64 nsz2 = pack2(-pz[0], -pz[0]);
        #pragma unroll
        for (int j = 0; j < PAIRS; j++) {
            u64 dx = add2(ppx[j], nsx2);
            u64 dy = add2(ppy[j], nsy2);
            u64 dz = add2(ppz[j], nsz2);
            u64 t  = add2(add2(mul2(dx, dx), mul2(dy, dy)), mul2(dz, dz));
            float t0, t1;
            unpack2(t, t0, t1);
            tmin[2 * j + 0] = t0;
            tmin[2 * j + 1] = t1;
            cmax = fmaxf(cmax, fmaxf(t0, t1));
        }
    }

    float* outb = out + (size_t)blockIdx.x * NSAMP * 3;

    for (int s = 0; s < NSAMP; s++) {
        const int par = s & 1;                        // SMEM double-buffer parity

        // ---- local winner: min index among slots with sqrt_rn(t) == sqrt_rn(cmax) ----
        const float a = __fsqrt_rn(cmax);
        const unsigned a_bits = __float_as_uint(a);   // a >= 0: bits monotone in value
        float pre = -1.0f;                            // a==0 degenerate: all qualify
        if (a > 0.0f) {
            float p = __uint_as_float(a_bits - 1u);   // pred(a)
            pre = __fmul_rd(p, p);                    // <= lower edge of a's sqrt bucket
        }

        unsigned cand = FULLMASK;
        #pragma unroll
        for (int j = 0; j < SLOTS; j++) {
            if (tmin[j] >= pre) {                     // rare beyond the max slot itself
                if (__fsqrt_rn(tmin[j]) == a) {
                    unsigned idx = (unsigned)(j * NTHREADS + tid);
                    cand = min(cand, idx);
                }
            }
        }
        // cand is always set: the slot achieving cmax qualifies.

        // ---- stage 1: warp reduce via REDUX (max sqrt bits, then min index) ----
        const unsigned w_amax = __reduce_max_sync(FULLMASK, a_bits);
        const unsigned w_idx  = __reduce_min_sync(FULLMASK,
                                  (a_bits == w_amax) ? cand : FULLMASK);
        if (lane == 0) {
            wa[par * NWARPS + wid] = w_amax;
            wi[par * NWARPS + wid] = w_idx;
        }
        __syncthreads();

        // ---- stage 2: every warp redundantly reduces the 32 partials ----
        const unsigned pa = wa[par * NWARPS + lane];
        const unsigned pi = wi[par * NWARPS + lane];
        const unsigned b_amax = __reduce_max_sync(FULLMASK, pa);
        const unsigned widx   = __reduce_min_sync(FULLMASK,
                                  (pa == b_amax) ? pi : FULLMASK);

        // selected point coords (broadcast LDS — conflict-free)
        const float sx = px[widx], sy = py[widx], sz = pz[widx];
        if (tid == 0) {
            outb[3 * s + 0] = sx;
            outb[3 * s + 1] = sy;
            outb[3 * s + 2] = sz;
        }

        // ---- packed min-update of squared-distance field; fuse next local max ----
        const u64 nsx2 = pack2(-sx, -sx);
        const u64 nsy2 = pack2(-sy, -sy);
        const u64 nsz2 = pack2(-sz, -sz);
        float cmax_next = -1.0f;
        #pragma unroll
        for (int j = 0; j < PAIRS; j++) {
            u64 dx = add2(ppx[j], nsx2);
            u64 dy = add2(ppy[j], nsy2);
            u64 dz = add2(ppz[j], nsz2);
            u64 t  = add2(add2(mul2(dx, dx), mul2(dy, dy)), mul2(dz, dz));
            float t0, t1;
            unpack2(t, t0, t1);
            float m0 = fminf(tmin[2 * j + 0], t0);
            float m1 = fminf(tmin[2 * j + 1], t1);
            tmin[2 * j + 0] = m0;
            tmin[2 * j + 1] = m1;
            cmax_next = fmaxf(cmax_next, fmaxf(m0, m1));
        }
        cmax = cmax_next;
    }
}

extern "C" void kernel_launch(void* const* d_in, const int* in_sizes, int n_in,
                              void* d_out, int out_size)
{
    const float* in  = (const float*)d_in[0];
    float*       out = (float*)d_out;

    const int B = in_sizes[0] / (NPTS * 3);   // 4

    const size_t smem = (size_t)(3 * NPTS) * sizeof(float)
                      + 4 * NWARPS * sizeof(unsigned);

    // Required: dynamic SMEM ~96.5 KB exceeds the 48 KB default. Idempotent;
    // not a stream op, not an allocation — safe under graph capture.
    (void)cudaFuncSetAttribute(fps_kernel,
                               cudaFuncAttributeMaxDynamicSharedMemorySize,
                               (int)smem);

    fps_kernel<<<B, NTHREADS, smem>>>(in, out);
}

// round 13
// speedup vs baseline: 1.3842x; 1.3842x over previous
#include <cuda_runtime.h>
#include <cstdint>

// FPS: B=4 batches, N=8192 points, S=1024 samples.
// Cluster of 8 CTAs per batch (grid = 4*8), 1024 threads/CTA -> exactly ONE
// point per thread. Per-iteration global argmax via:
//   warp REDUX -> __syncthreads -> warp0 block REDUX -> DSMEM mailbox
//   all-to-all (packed key) -> cluster.sync -> 8-key shfl max.
// Exact float32 decision reproduction (rel_err 0.0 confirmed in R8 with the
// same arithmetic): squared-domain running min (commutes with monotone
// sqrt_rn); per-thread a = sqrt_rn(tmin) IS its ds value, so REDUX max on
// bits + min-index select reproduces jnp.argmax first-occurrence ties with
// no prefilter machinery. Distance: __fadd_rn/__fmul_rn, (dx^2+dy^2)+dz^2.

#define NPTS     8192
#define NSAMP    1024
#define CLUSTER  8
#define NTHREADS 1024                 // points per CTA = NPTS/CLUSTER = 1024
#define NWARPS   (NTHREADS / 32)      // 32
#define FULLMASK 0xffffffffu

typedef unsigned long long u64;

__global__ __launch_bounds__(NTHREADS, 1) __cluster_dims__(CLUSTER, 1, 1)
void fps_kernel(const float* __restrict__ in, float* __restrict__ out)
{
    extern __shared__ float sm[];
    float*    px   = sm;                         // [NPTS] full batch table
    float*    py   = sm + NPTS;                  // [NPTS]
    float*    pz   = sm + 2 * NPTS;              // [NPTS]
    unsigned* wa   = (unsigned*)(sm + 3 * NPTS); // [2][NWARPS] sqrt bits
    unsigned* wi   = wa + 2 * NWARPS;            // [2][NWARPS] min index
    u64*      mbox = (u64*)(wi + 2 * NWARPS);    // [2][CLUSTER] packed keys

    const int tid  = threadIdx.x;
    const int lane = tid & 31;
    const int wid  = tid >> 5;

    unsigned rank;
    asm("mov.u32 %0, %%cluster_ctarank;" : "=r"(rank));
    const int batch = blockIdx.x / CLUSTER;

    const float* g = in + (size_t)batch * NPTS * 3;

    // ---- load full batch point table (one-time) ----
    for (int i = tid; i < NPTS; i += NTHREADS) {
        px[i] = g[3 * i + 0];
        py[i] = g[3 * i + 1];
        pz[i] = g[3 * i + 2];
    }
    __syncthreads();

    // ---- this thread's single point ----
    const unsigned myidx = rank * NTHREADS + (unsigned)tid;   // global in batch
    const float mx = px[myidx], myy = py[myidx], mz = pz[myidx];

    // ---- init: squared distance to point 0; a = ds value ----
    float tmin;
    {
        float dx = __fadd_rn(mx,  -px[0]);
        float dy = __fadd_rn(myy, -py[0]);
        float dz = __fadd_rn(mz,  -pz[0]);
        tmin = __fadd_rn(__fadd_rn(__fmul_rn(dx, dx), __fmul_rn(dy, dy)),
                         __fmul_rn(dz, dz));
    }
    float a = __fsqrt_rn(tmin);

    float* outb = out + (size_t)batch * NSAMP * 3;

    // startup cluster sync: all CTAs ready before first remote mailbox write
    asm volatile("barrier.cluster.arrive.aligned;" ::: "memory");
    asm volatile("barrier.cluster.wait.aligned;" ::: "memory");

    for (int s = 0; s < NSAMP; s++) {
        const int par = s & 1;                       // double-buffer parity
        const unsigned a_bits = __float_as_uint(a);  // a >= 0: bits monotone

        // ---- stage 1: warp REDUX (max ds bits, then min index among max) ----
        const unsigned w_amax = __reduce_max_sync(FULLMASK, a_bits);
        const unsigned w_idx  = __reduce_min_sync(FULLMASK,
                                  (a_bits == w_amax) ? myidx : FULLMASK);
        if (lane == 0) {
            wa[par * NWARPS + wid] = w_amax;
            wi[par * NWARPS + wid] = w_idx;
        }
        __syncthreads();

        // ---- stage 2 (warp 0 only): CTA winner -> mailbox of all 8 CTAs ----
        if (wid == 0) {
            const unsigned pa = wa[par * NWARPS + lane];
            const unsigned pi = wi[par * NWARPS + lane];
            const unsigned b_amax = __reduce_max_sync(FULLMASK, pa);
            const unsigned b_idx  = __reduce_min_sync(FULLMASK,
                                      (pa == b_amax) ? pi : FULLMASK);
            if (lane == 0) {
                // key orders by (ds desc, index asc)
                const u64 key = ((u64)b_amax << 32) |
                                (u64)(FULLMASK - b_idx);
                unsigned laddr = (unsigned)__cvta_generic_to_shared(
                                     &mbox[par * CLUSTER + rank]);
                #pragma unroll
                for (unsigned r = 0; r < CLUSTER; r++) {
                    unsigned raddr;
                    asm("mapa.shared::cluster.u32 %0, %1, %2;"
                        : "=r"(raddr) : "r"(laddr), "r"(r));
                    asm volatile("st.shared::cluster.u64 [%0], %1;"
                                 :: "r"(raddr), "l"(key) : "memory");
                }
            }
        }

        // arrive.release / wait.acquire: remote stores visible after this
        asm volatile("barrier.cluster.arrive.aligned;" ::: "memory");
        asm volatile("barrier.cluster.wait.aligned;" ::: "memory");

        // ---- final: max over 8 keys via 3-step u64 shfl (lanes in groups of 8) ----
        u64 k = mbox[par * CLUSTER + (lane & 7)];
        #pragma unroll
        for (int off = 1; off <= 4; off <<= 1) {
            u64 o = __shfl_xor_sync(FULLMASK, k, off);
            if (o > k) k = o;
        }
        const unsigned widx = FULLMASK - (unsigned)(k & 0xffffffffu);

        // selected point coords (broadcast LDS from local full table)
        const float sx = px[widx], sy = py[widx], sz = pz[widx];
        if (rank == 0 && tid == 0) {
            outb[3 * s + 0] = sx;
            outb[3 * s + 1] = sy;
            outb[3 * s + 2] = sz;
        }

        // ---- scalar min-update of this thread's single point ----
        float dx = __fadd_rn(mx,  -sx);
        float dy = __fadd_rn(myy, -sy);
        float dz = __fadd_rn(mz,  -sz);
        float t  = __fadd_rn(__fadd_rn(__fmul_rn(dx, dx), __fmul_rn(dy, dy)),
                             __fmul_rn(dz, dz));
        tmin = fminf(tmin, t);
        a = __fsqrt_rn(tmin);
    }
}

extern "C" void kernel_launch(void* const* d_in, const int* in_sizes, int n_in,
                              void* d_out, int out_size)
{
    const float* in  = (const float*)d_in[0];
    float*       out = (float*)d_out;

    const int B = in_sizes[0] / (NPTS * 3);   // 4

    const size_t smem = (size_t)(3 * NPTS) * sizeof(float)     // point table
                      + 4 * NWARPS * sizeof(unsigned)           // partials x2 buf
                      + 2 * CLUSTER * sizeof(u64);              // mailbox x2 buf

    // Required: dynamic SMEM ~96.6 KB exceeds the 48 KB default. Idempotent;
    // not a stream op, not an allocation — safe under graph capture.
    (void)cudaFuncSetAttribute(fps_kernel,
                               cudaFuncAttributeMaxDynamicSharedMemorySize,
                               (int)smem);

    fps_kernel<<<B * CLUSTER, NTHREADS, smem>>>(in, out);
}